// round 8
// baseline (speedup 1.0000x reference)
#include <cuda_runtime.h>
#include <cuda_bf16.h>
#include <cstdint>

#define MAX_ATOMS 40000
#define MAX_EDGES 640000
#define NFM 128

// ---------------------------------------------------------------------------
// Scratch
// ---------------------------------------------------------------------------
__device__ float    g_f[(size_t)MAX_ATOMS * NFM];     // f = x @ W_in
__device__ float    g_conv[(size_t)MAX_ATOMS * NFM];  // segment-summed conv
__device__ int      g_rowstart[MAX_ATOMS + 1];        // CSR offsets
// Pre-packed B fragments in mma.m16n8k16 register order.
// [matrix: 0=Win 1=Wout][term: 0=hi 1=lo][ ((t*8+k)*32+lane)*2 + reg ]
__device__ uint32_t g_Bfrag[2][2][8192];

// ---------------------------------------------------------------------------
__device__ __forceinline__ void split_pair(float v0, float v1,
                                           uint32_t& hp, uint32_t& lp) {
    __nv_bfloat16 h0 = __float2bfloat16(v0);
    __nv_bfloat16 h1 = __float2bfloat16(v1);
    __nv_bfloat16 l0 = __float2bfloat16(v0 - __bfloat162float(h0));
    __nv_bfloat16 l1 = __float2bfloat16(v1 - __bfloat162float(h1));
    hp = (uint32_t)__bfloat16_as_ushort(h0) | ((uint32_t)__bfloat16_as_ushort(h1) << 16);
    lp = (uint32_t)__bfloat16_as_ushort(l0) | ((uint32_t)__bfloat16_as_ushort(l1) << 16);
}

__device__ __forceinline__ void mma16816(float* c, const uint32_t* a,
                                         uint32_t b0, uint32_t b1) {
    asm volatile(
        "mma.sync.aligned.m16n8k16.row.col.f32.bf16.bf16.f32 "
        "{%0,%1,%2,%3}, {%4,%5,%6,%7}, {%8,%9}, {%0,%1,%2,%3};"
        : "+f"(c[0]), "+f"(c[1]), "+f"(c[2]), "+f"(c[3])
        : "r"(a[0]), "r"(a[1]), "r"(a[2]), "r"(a[3]), "r"(b0), "r"(b1));
}

// ---------------------------------------------------------------------------
// Prep: pack weights into B-fragment order, split hi/lo. W is [K,N] row-major.
// ---------------------------------------------------------------------------
__global__ void prep_weights_kernel(const float* __restrict__ W_in,
                                    const float* __restrict__ W_out)
{
    int id = blockIdx.x * blockDim.x + threadIdx.x;   // 0..32767
    int reg  = id & 1;
    int lane = (id >> 1) & 31;
    int k    = (id >> 6) & 7;
    int t    = (id >> 9) & 15;
    int term = (id >> 13) & 1;
    int mat  = (id >> 14) & 1;

    const float* W = mat ? W_out : W_in;
    int kr = k * 16 + (lane & 3) * 2 + reg * 8;
    int n  = t * 8 + (lane >> 2);
    float v0 = W[(size_t)kr * 128 + n];
    float v1 = W[(size_t)(kr + 1) * 128 + n];
    uint32_t hp, lp;
    split_pair(v0, v1, hp, lp);
    g_Bfrag[mat][term][(((t * 8 + k) * 32) + lane) * 2 + reg] = term ? lp : hp;
}

// ---------------------------------------------------------------------------
// GEMM via mma.sync: C[M,128] = A[M,128] @ W[128,128] (+bias).
// Split bf16 3-term. CTA: 64x128 tile, 8 warps (warp tile 32x32), 2 CTAs/SM.
// ---------------------------------------------------------------------------
#define A_STRIDE 136   // bf16 elems per row (bank-conflict-free)

__global__ __launch_bounds__(256, 2)
void gemm_mma_kernel(const float* __restrict__ A,
                     const uint32_t* __restrict__ Bh,
                     const uint32_t* __restrict__ Bl,
                     const float* __restrict__ bias,
                     float* __restrict__ C, int M)
{
    extern __shared__ __nv_bfloat16 sA[];     // [2][64][A_STRIDE]
    __nv_bfloat16* Ah = sA;
    __nv_bfloat16* Al = sA + 64 * A_STRIDE;

    const int tid = threadIdx.x;
    const int m0  = blockIdx.x * 64;

#pragma unroll
    for (int it = 0; it < 16; it++) {
        int p  = tid + it * 256;
        int m  = p >> 6;
        int kp = (p & 63) << 1;
        float2 v = make_float2(0.f, 0.f);
        if (m0 + m < M)
            v = *reinterpret_cast<const float2*>(&A[(size_t)(m0 + m) * 128 + kp]);
        uint32_t hp, lp;
        split_pair(v.x, v.y, hp, lp);
        *reinterpret_cast<uint32_t*>(&Ah[m * A_STRIDE + kp]) = hp;
        *reinterpret_cast<uint32_t*>(&Al[m * A_STRIDE + kp]) = lp;
    }
    __syncthreads();

    const int wid  = tid >> 5;
    const int lane = tid & 31;
    const int wm   = wid & 1;
    const int wn   = wid >> 1;
    const int g    = lane >> 2;
    const int tg   = lane & 3;

    float acc[2][4][4];
#pragma unroll
    for (int mf = 0; mf < 2; mf++)
#pragma unroll
        for (int t4 = 0; t4 < 4; t4++)
#pragma unroll
            for (int i = 0; i < 4; i++) acc[mf][t4][i] = 0.f;

#pragma unroll
    for (int k = 0; k < 8; k++) {
        uint32_t ah[2][4], al[2][4];
        const int cb = k * 16 + tg * 2;
#pragma unroll
        for (int mf = 0; mf < 2; mf++) {
            int r = wm * 32 + mf * 16 + g;
            ah[mf][0] = *reinterpret_cast<const uint32_t*>(&Ah[r * A_STRIDE + cb]);
            ah[mf][1] = *reinterpret_cast<const uint32_t*>(&Ah[(r + 8) * A_STRIDE + cb]);
            ah[mf][2] = *reinterpret_cast<const uint32_t*>(&Ah[r * A_STRIDE + cb + 8]);
            ah[mf][3] = *reinterpret_cast<const uint32_t*>(&Ah[(r + 8) * A_STRIDE + cb + 8]);
            al[mf][0] = *reinterpret_cast<const uint32_t*>(&Al[r * A_STRIDE + cb]);
            al[mf][1] = *reinterpret_cast<const uint32_t*>(&Al[(r + 8) * A_STRIDE + cb]);
            al[mf][2] = *reinterpret_cast<const uint32_t*>(&Al[r * A_STRIDE + cb + 8]);
            al[mf][3] = *reinterpret_cast<const uint32_t*>(&Al[(r + 8) * A_STRIDE + cb + 8]);
        }
#pragma unroll
        for (int t4 = 0; t4 < 4; t4++) {
            int fidx = (((wn * 4 + t4) * 8 + k) * 32 + lane) * 2;
            uint32_t bh0 = __ldg(&Bh[fidx]);
            uint32_t bh1 = __ldg(&Bh[fidx + 1]);
            uint32_t bl0 = __ldg(&Bl[fidx]);
            uint32_t bl1 = __ldg(&Bl[fidx + 1]);
#pragma unroll
            for (int mf = 0; mf < 2; mf++) {
                mma16816(acc[mf][t4], ah[mf], bh0, bh1);
                mma16816(acc[mf][t4], ah[mf], bl0, bl1);
                mma16816(acc[mf][t4], al[mf], bh0, bh1);
            }
        }
    }

#pragma unroll
    for (int t4 = 0; t4 < 4; t4++) {
        int col = wn * 32 + t4 * 8 + tg * 2;
        float b0 = bias ? __ldg(&bias[col])     : 0.f;
        float b1 = bias ? __ldg(&bias[col + 1]) : 0.f;
#pragma unroll
        for (int mf = 0; mf < 2; mf++) {
            int row = m0 + wm * 32 + mf * 16 + g;
            if (row < M) {
                float2 o0 = make_float2(acc[mf][t4][0] + b0, acc[mf][t4][1] + b1);
                *reinterpret_cast<float2*>(&C[(size_t)row * 128 + col]) = o0;
            }
            if (row + 8 < M) {
                float2 o1 = make_float2(acc[mf][t4][2] + b0, acc[mf][t4][3] + b1);
                *reinterpret_cast<float2*>(&C[(size_t)(row + 8) * 128 + col]) = o1;
            }
        }
    }
}

// ---------------------------------------------------------------------------
// CSR offsets from sorted seg_i
// ---------------------------------------------------------------------------
__global__ void offsets_kernel(const int* __restrict__ seg_i, int num_edges, int num_atoms)
{
    int a = blockIdx.x * blockDim.x + threadIdx.x;
    if (a > num_atoms) return;
    int lo = 0, hi = num_edges;
    while (lo < hi) {
        int mid = (lo + hi) >> 1;
        if (seg_i[mid] < a) lo = mid + 1; else hi = mid;
    }
    g_rowstart[a] = lo;
}

// ---------------------------------------------------------------------------
// Edge kernel: one warp per TWO consecutive atoms (interleaved chains).
// Block = 16 consecutive atoms -> contiguous w_ij stream per block.
// Lane owns 4 channels. Index prefetch breaks idx->gather chain.
// ---------------------------------------------------------------------------
__global__ __launch_bounds__(256)
void conv_kernel(const float* __restrict__ w_ij, const int* __restrict__ idx_j,
                 int num_atoms)
{
    const int warp = threadIdx.x >> 5;
    const int lane = threadIdx.x & 31;
    const int c    = lane * 4;
    const int a0   = blockIdx.x * 16 + warp * 2;
    if (a0 >= num_atoms) return;
    const bool hasB = (a0 + 1) < num_atoms;

    const int sA = g_rowstart[a0];
    const int eA = g_rowstart[a0 + 1];
    const int eB = hasB ? g_rowstart[a0 + 2] : eA;

    float4 acc0 = make_float4(0.f, 0.f, 0.f, 0.f);
    float4 acc1 = make_float4(0.f, 0.f, 0.f, 0.f);

    int kA = sA, kB = eA;

    int jA0 = 0, jA1 = 0, jB0 = 0, jB1 = 0;
    bool pA = (kA + 1 < eA), pB = (kB + 1 < eB);
    if (pA) { jA0 = __ldg(&idx_j[kA]); jA1 = __ldg(&idx_j[kA + 1]); }
    if (pB) { jB0 = __ldg(&idx_j[kB]); jB1 = __ldg(&idx_j[kB + 1]); }

    while (pA && pB) {
        // prefetch next iteration's indices
        int nA0 = 0, nA1 = 0, nB0 = 0, nB1 = 0;
        const bool nxA = (kA + 3 < eA), nxB = (kB + 3 < eB);
        if (nxA) { nA0 = __ldg(&idx_j[kA + 2]); nA1 = __ldg(&idx_j[kA + 3]); }
        if (nxB) { nB0 = __ldg(&idx_j[kB + 2]); nB1 = __ldg(&idx_j[kB + 3]); }

        float4 wA0 = __ldcs(reinterpret_cast<const float4*>(&w_ij[(size_t)kA * 128 + c]));
        float4 wA1 = __ldcs(reinterpret_cast<const float4*>(&w_ij[(size_t)(kA + 1) * 128 + c]));
        float4 wB0 = __ldcs(reinterpret_cast<const float4*>(&w_ij[(size_t)kB * 128 + c]));
        float4 wB1 = __ldcs(reinterpret_cast<const float4*>(&w_ij[(size_t)(kB + 1) * 128 + c]));
        float4 fA0 = __ldg(reinterpret_cast<const float4*>(&g_f[(size_t)jA0 * 128 + c]));
        float4 fA1 = __ldg(reinterpret_cast<const float4*>(&g_f[(size_t)jA1 * 128 + c]));
        float4 fB0 = __ldg(reinterpret_cast<const float4*>(&g_f[(size_t)jB0 * 128 + c]));
        float4 fB1 = __ldg(reinterpret_cast<const float4*>(&g_f[(size_t)jB1 * 128 + c]));

        acc0.x = fmaf(wA0.x, fA0.x, acc0.x); acc0.y = fmaf(wA0.y, fA0.y, acc0.y);
        acc0.z = fmaf(wA0.z, fA0.z, acc0.z); acc0.w = fmaf(wA0.w, fA0.w, acc0.w);
        acc0.x = fmaf(wA1.x, fA1.x, acc0.x); acc0.y = fmaf(wA1.y, fA1.y, acc0.y);
        acc0.z = fmaf(wA1.z, fA1.z, acc0.z); acc0.w = fmaf(wA1.w, fA1.w, acc0.w);
        acc1.x = fmaf(wB0.x, fB0.x, acc1.x); acc1.y = fmaf(wB0.y, fB0.y, acc1.y);
        acc1.z = fmaf(wB0.z, fB0.z, acc1.z); acc1.w = fmaf(wB0.w, fB0.w, acc1.w);
        acc1.x = fmaf(wB1.x, fB1.x, acc1.x); acc1.y = fmaf(wB1.y, fB1.y, acc1.y);
        acc1.z = fmaf(wB1.z, fB1.z, acc1.z); acc1.w = fmaf(wB1.w, fB1.w, acc1.w);

        kA += 2; kB += 2;
        jA0 = nA0; jA1 = nA1; jB0 = nB0; jB1 = nB1;
        pA = nxA; pB = nxB;
    }

    // drain A
    for (; kA < eA; kA++) {
        int j = __ldg(&idx_j[kA]);
        float4 w = __ldcs(reinterpret_cast<const float4*>(&w_ij[(size_t)kA * 128 + c]));
        float4 f = __ldg(reinterpret_cast<const float4*>(&g_f[(size_t)j * 128 + c]));
        acc0.x = fmaf(w.x, f.x, acc0.x); acc0.y = fmaf(w.y, f.y, acc0.y);
        acc0.z = fmaf(w.z, f.z, acc0.z); acc0.w = fmaf(w.w, f.w, acc0.w);
    }
    // drain B
    for (; kB < eB; kB++) {
        int j = __ldg(&idx_j[kB]);
        float4 w = __ldcs(reinterpret_cast<const float4*>(&w_ij[(size_t)kB * 128 + c]));
        float4 f = __ldg(reinterpret_cast<const float4*>(&g_f[(size_t)j * 128 + c]));
        acc1.x = fmaf(w.x, f.x, acc1.x); acc1.y = fmaf(w.y, f.y, acc1.y);
        acc1.z = fmaf(w.z, f.z, acc1.z); acc1.w = fmaf(w.w, f.w, acc1.w);
    }

    *reinterpret_cast<float4*>(&g_conv[(size_t)a0 * 128 + c]) = acc0;
    if (hasB)
        *reinterpret_cast<float4*>(&g_conv[(size_t)(a0 + 1) * 128 + c]) = acc1;
}

// ---------------------------------------------------------------------------
extern "C" void kernel_launch(void* const* d_in, const int* in_sizes, int n_in,
                              void* d_out, int out_size)
{
    const float* x    = (const float*)d_in[0];
    const float* wij  = (const float*)d_in[1];
    const int*   seg  = (const int*)d_in[2];
    const int*   idxj = (const int*)d_in[3];
    int base = 4;
    if (n_in >= 8 && in_sizes[4] == 1) base = 5;   // skip scalar seg_i_sum
    const float* Win  = (const float*)d_in[base];
    const float* Wout = (const float*)d_in[base + 1];
    const float* bout = (const float*)d_in[base + 2];

    int num_edges = in_sizes[2];
    int num_atoms = out_size / NFM;
    if (num_atoms > MAX_ATOMS) num_atoms = MAX_ATOMS;
    if (num_edges > MAX_EDGES) num_edges = MAX_EDGES;

    float*    f_ptr    = nullptr;
    float*    conv_ptr = nullptr;
    uint32_t* bfrag    = nullptr;
    cudaGetSymbolAddress((void**)&f_ptr, g_f);
    cudaGetSymbolAddress((void**)&conv_ptr, g_conv);
    cudaGetSymbolAddress((void**)&bfrag, g_Bfrag);

    const int SMEM_A = 2 * 64 * A_STRIDE * (int)sizeof(__nv_bfloat16);  // 34816
    cudaFuncSetAttribute(gemm_mma_kernel,
                         cudaFuncAttributeMaxDynamicSharedMemorySize, SMEM_A);

    int gblocks = (num_atoms + 63) / 64;

    // 0) pack weights into mma B fragments (hi/lo)
    prep_weights_kernel<<<128, 256>>>(Win, Wout);

    // 1) CSR offsets
    offsets_kernel<<<(num_atoms + 1 + 255) / 256, 256>>>(seg, num_edges, num_atoms);

    // 2) f = x @ W_in
    gemm_mma_kernel<<<gblocks, 256, SMEM_A>>>(
        x, bfrag + 0 * 8192, bfrag + 1 * 8192, nullptr, f_ptr, num_atoms);

    // 3) conv = segment_sum(w_ij * f[idx_j])
    conv_kernel<<<(num_atoms + 15) / 16, 256>>>(wij, idxj, num_atoms);

    // 4) out = conv @ W_out + b_out
    gemm_mma_kernel<<<gblocks, 256, SMEM_A>>>(
        conv_ptr, bfrag + 2 * 8192, bfrag + 3 * 8192, bout, (float*)d_out, num_atoms);
}

// round 9
// speedup vs baseline: 1.3675x; 1.3675x over previous
#include <cuda_runtime.h>
#include <cuda_bf16.h>
#include <cstdint>

#define MAX_ATOMS 40000
#define MAX_EDGES 640000
#define NFM 128

// ---------------------------------------------------------------------------
// Scratch
// ---------------------------------------------------------------------------
__device__ float    g_f[(size_t)MAX_ATOMS * NFM];     // f = x @ W_in
__device__ float    g_conv[(size_t)MAX_ATOMS * NFM];  // segment-summed conv
// Pre-packed B fragments in mma.m16n8k16 register order.
// [matrix: 0=Win 1=Wout][term: 0=hi 1=lo][ ((t*8+k)*32+lane)*2 + reg ]
__device__ uint32_t g_Bfrag[2][2][8192];

// ---------------------------------------------------------------------------
__device__ __forceinline__ void split_pair(float v0, float v1,
                                           uint32_t& hp, uint32_t& lp) {
    __nv_bfloat16 h0 = __float2bfloat16(v0);
    __nv_bfloat16 h1 = __float2bfloat16(v1);
    __nv_bfloat16 l0 = __float2bfloat16(v0 - __bfloat162float(h0));
    __nv_bfloat16 l1 = __float2bfloat16(v1 - __bfloat162float(h1));
    hp = (uint32_t)__bfloat16_as_ushort(h0) | ((uint32_t)__bfloat16_as_ushort(h1) << 16);
    lp = (uint32_t)__bfloat16_as_ushort(l0) | ((uint32_t)__bfloat16_as_ushort(l1) << 16);
}

__device__ __forceinline__ void mma16816(float* c, const uint32_t* a,
                                         uint32_t b0, uint32_t b1) {
    asm volatile(
        "mma.sync.aligned.m16n8k16.row.col.f32.bf16.bf16.f32 "
        "{%0,%1,%2,%3}, {%4,%5,%6,%7}, {%8,%9}, {%0,%1,%2,%3};"
        : "+f"(c[0]), "+f"(c[1]), "+f"(c[2]), "+f"(c[3])
        : "r"(a[0]), "r"(a[1]), "r"(a[2]), "r"(a[3]), "r"(b0), "r"(b1));
}

// ---------------------------------------------------------------------------
// Prep: pack weights into B-fragment order, split hi/lo. W is [K,N] row-major.
// ---------------------------------------------------------------------------
__global__ void prep_weights_kernel(const float* __restrict__ W_in,
                                    const float* __restrict__ W_out)
{
    int id = blockIdx.x * blockDim.x + threadIdx.x;   // 0..32767
    int reg  = id & 1;
    int lane = (id >> 1) & 31;
    int k    = (id >> 6) & 7;
    int t    = (id >> 9) & 15;
    int term = (id >> 13) & 1;
    int mat  = (id >> 14) & 1;

    const float* W = mat ? W_out : W_in;
    int kr = k * 16 + (lane & 3) * 2 + reg * 8;
    int n  = t * 8 + (lane >> 2);
    float v0 = W[(size_t)kr * 128 + n];
    float v1 = W[(size_t)(kr + 1) * 128 + n];
    uint32_t hp, lp;
    split_pair(v0, v1, hp, lp);
    g_Bfrag[mat][term][(((t * 8 + k) * 32) + lane) * 2 + reg] = term ? lp : hp;
}

// ---------------------------------------------------------------------------
// Zero g_conv (atoms with no edges + atomic targets need zeroed rows).
// ---------------------------------------------------------------------------
__global__ void zero_conv_kernel(int n_float4)
{
    int i = blockIdx.x * blockDim.x + threadIdx.x;
    if (i < n_float4)
        reinterpret_cast<float4*>(g_conv)[i] = make_float4(0.f, 0.f, 0.f, 0.f);
}

// ---------------------------------------------------------------------------
// GEMM via mma.sync: C[M,128] = A[M,128] @ W[128,128] (+bias).
// Split bf16 3-term. CTA: 64x128 tile, 8 warps (warp tile 32x32), 2 CTAs/SM.
// ---------------------------------------------------------------------------
#define A_STRIDE 136   // bf16 elems per row (bank-conflict-free)

__global__ __launch_bounds__(256, 2)
void gemm_mma_kernel(const float* __restrict__ A,
                     const uint32_t* __restrict__ Bh,
                     const uint32_t* __restrict__ Bl,
                     const float* __restrict__ bias,
                     float* __restrict__ C, int M)
{
    extern __shared__ __nv_bfloat16 sA[];     // [2][64][A_STRIDE]
    __nv_bfloat16* Ah = sA;
    __nv_bfloat16* Al = sA + 64 * A_STRIDE;

    const int tid = threadIdx.x;
    const int m0  = blockIdx.x * 64;

#pragma unroll
    for (int it = 0; it < 16; it++) {
        int p  = tid + it * 256;
        int m  = p >> 6;
        int kp = (p & 63) << 1;
        float2 v = make_float2(0.f, 0.f);
        if (m0 + m < M)
            v = *reinterpret_cast<const float2*>(&A[(size_t)(m0 + m) * 128 + kp]);
        uint32_t hp, lp;
        split_pair(v.x, v.y, hp, lp);
        *reinterpret_cast<uint32_t*>(&Ah[m * A_STRIDE + kp]) = hp;
        *reinterpret_cast<uint32_t*>(&Al[m * A_STRIDE + kp]) = lp;
    }
    __syncthreads();

    const int wid  = tid >> 5;
    const int lane = tid & 31;
    const int wm   = wid & 1;
    const int wn   = wid >> 1;
    const int g    = lane >> 2;
    const int tg   = lane & 3;

    float acc[2][4][4];
#pragma unroll
    for (int mf = 0; mf < 2; mf++)
#pragma unroll
        for (int t4 = 0; t4 < 4; t4++)
#pragma unroll
            for (int i = 0; i < 4; i++) acc[mf][t4][i] = 0.f;

#pragma unroll
    for (int k = 0; k < 8; k++) {
        uint32_t ah[2][4], al[2][4];
        const int cb = k * 16 + tg * 2;
#pragma unroll
        for (int mf = 0; mf < 2; mf++) {
            int r = wm * 32 + mf * 16 + g;
            ah[mf][0] = *reinterpret_cast<const uint32_t*>(&Ah[r * A_STRIDE + cb]);
            ah[mf][1] = *reinterpret_cast<const uint32_t*>(&Ah[(r + 8) * A_STRIDE + cb]);
            ah[mf][2] = *reinterpret_cast<const uint32_t*>(&Ah[r * A_STRIDE + cb + 8]);
            ah[mf][3] = *reinterpret_cast<const uint32_t*>(&Ah[(r + 8) * A_STRIDE + cb + 8]);
            al[mf][0] = *reinterpret_cast<const uint32_t*>(&Al[r * A_STRIDE + cb]);
            al[mf][1] = *reinterpret_cast<const uint32_t*>(&Al[(r + 8) * A_STRIDE + cb]);
            al[mf][2] = *reinterpret_cast<const uint32_t*>(&Al[r * A_STRIDE + cb + 8]);
            al[mf][3] = *reinterpret_cast<const uint32_t*>(&Al[(r + 8) * A_STRIDE + cb + 8]);
        }
#pragma unroll
        for (int t4 = 0; t4 < 4; t4++) {
            int fidx = (((wn * 4 + t4) * 8 + k) * 32 + lane) * 2;
            uint32_t bh0 = __ldg(&Bh[fidx]);
            uint32_t bh1 = __ldg(&Bh[fidx + 1]);
            uint32_t bl0 = __ldg(&Bl[fidx]);
            uint32_t bl1 = __ldg(&Bl[fidx + 1]);
#pragma unroll
            for (int mf = 0; mf < 2; mf++) {
                mma16816(acc[mf][t4], ah[mf], bh0, bh1);
                mma16816(acc[mf][t4], ah[mf], bl0, bl1);
                mma16816(acc[mf][t4], al[mf], bh0, bh1);
            }
        }
    }

#pragma unroll
    for (int t4 = 0; t4 < 4; t4++) {
        int col = wn * 32 + t4 * 8 + tg * 2;
        float b0 = bias ? __ldg(&bias[col])     : 0.f;
        float b1 = bias ? __ldg(&bias[col + 1]) : 0.f;
#pragma unroll
        for (int mf = 0; mf < 2; mf++) {
            int row = m0 + wm * 32 + mf * 16 + g;
            if (row < M) {
                float2 o0 = make_float2(acc[mf][t4][0] + b0, acc[mf][t4][1] + b1);
                *reinterpret_cast<float2*>(&C[(size_t)row * 128 + col]) = o0;
            }
            if (row + 8 < M) {
                float2 o1 = make_float2(acc[mf][t4][2] + b0, acc[mf][t4][3] + b1);
                *reinterpret_cast<float2*>(&C[(size_t)(row + 8) * 128 + col]) = o1;
            }
        }
    }
}

// ---------------------------------------------------------------------------
// Edge-centric conv: each warp owns 32 CONSECUTIVE edges -> perfectly
// sequential w_ij stream + perfect load balance. seg_i sorted -> register
// run accumulation; interior atoms direct-store, chunk-boundary atoms
// atomicAdd into zeroed g_conv.
// ---------------------------------------------------------------------------
#define EPW 32

__device__ __forceinline__ void flush_row(int atom, int c, const float4& acc,
                                          bool use_atomic)
{
    float* p = &g_conv[(size_t)atom * 128 + c];
    if (use_atomic) {
        atomicAdd(p + 0, acc.x);
        atomicAdd(p + 1, acc.y);
        atomicAdd(p + 2, acc.z);
        atomicAdd(p + 3, acc.w);
    } else {
        *reinterpret_cast<float4*>(p) = acc;
    }
}

__global__ __launch_bounds__(256)
void conv_edge_kernel(const float* __restrict__ w_ij,
                      const int* __restrict__ idx_j,
                      const int* __restrict__ seg_i,
                      int num_edges)
{
    const int wg   = blockIdx.x * 8 + (threadIdx.x >> 5);
    const int lane = threadIdx.x & 31;
    const int c    = lane * 4;
    const int kbeg = wg * EPW;
    if (kbeg >= num_edges) return;
    const int kend = min(kbeg + EPW, num_edges);

    int cur = __ldg(&seg_i[kbeg]);
    const int first_atom = cur;
    float4 acc = make_float4(0.f, 0.f, 0.f, 0.f);

    int k = kbeg;
    // current group state
    int j[4], s[4];
    int gsz = min(4, kend - k);
#pragma unroll
    for (int u = 0; u < 4; u++)
        if (u < gsz) { j[u] = __ldg(&idx_j[k + u]); s[u] = __ldg(&seg_i[k + u]); }

    while (k < kend) {
        // prefetch next group
        int nj[4], ns[4];
        const int nk = k + 4;
        const int ngsz = (nk < kend) ? min(4, kend - nk) : 0;
#pragma unroll
        for (int u = 0; u < 4; u++)
            if (u < ngsz) { nj[u] = __ldg(&idx_j[nk + u]); ns[u] = __ldg(&seg_i[nk + u]); }

        // load this group's w and f (independent loads, high MLP)
        float4 w4[4], f4[4];
#pragma unroll
        for (int u = 0; u < 4; u++) {
            if (u < gsz) {
                w4[u] = __ldcs(reinterpret_cast<const float4*>(&w_ij[(size_t)(k + u) * 128 + c]));
                f4[u] = __ldg(reinterpret_cast<const float4*>(&g_f[(size_t)j[u] * 128 + c]));
            }
        }

        // accumulate with run-break flushes (seg uniform across warp)
#pragma unroll
        for (int u = 0; u < 4; u++) {
            if (u < gsz) {
                acc.x = fmaf(w4[u].x, f4[u].x, acc.x);
                acc.y = fmaf(w4[u].y, f4[u].y, acc.y);
                acc.z = fmaf(w4[u].z, f4[u].z, acc.z);
                acc.w = fmaf(w4[u].w, f4[u].w, acc.w);
                // next edge's segment (within group, or first of next group)
                int nxt = -1;
                if (u + 1 < gsz)      nxt = s[u + 1];
                else if (ngsz > 0)    nxt = ns[0];
                if (nxt != cur) {
                    if (nxt >= 0) {
                        // mid-chunk flush: atomic only if atom may span backward
                        flush_row(cur, c, acc, cur == first_atom);
                        acc = make_float4(0.f, 0.f, 0.f, 0.f);
                        cur = nxt;
                    }
                    // nxt < 0: end of chunk; final flush after loop
                }
            }
        }

#pragma unroll
        for (int u = 0; u < 4; u++) { j[u] = nj[u]; s[u] = ns[u]; }
        k = nk;
        gsz = ngsz;
    }

    // final flush: atom may span forward into next chunk (and/or backward)
    flush_row(cur, c, acc, true);
}

// ---------------------------------------------------------------------------
extern "C" void kernel_launch(void* const* d_in, const int* in_sizes, int n_in,
                              void* d_out, int out_size)
{
    const float* x    = (const float*)d_in[0];
    const float* wij  = (const float*)d_in[1];
    const int*   seg  = (const int*)d_in[2];
    const int*   idxj = (const int*)d_in[3];
    int base = 4;
    if (n_in >= 8 && in_sizes[4] == 1) base = 5;   // skip scalar seg_i_sum
    const float* Win  = (const float*)d_in[base];
    const float* Wout = (const float*)d_in[base + 1];
    const float* bout = (const float*)d_in[base + 2];

    int num_edges = in_sizes[2];
    int num_atoms = out_size / NFM;
    if (num_atoms > MAX_ATOMS) num_atoms = MAX_ATOMS;
    if (num_edges > MAX_EDGES) num_edges = MAX_EDGES;

    float*    f_ptr    = nullptr;
    float*    conv_ptr = nullptr;
    uint32_t* bfrag    = nullptr;
    cudaGetSymbolAddress((void**)&f_ptr, g_f);
    cudaGetSymbolAddress((void**)&conv_ptr, g_conv);
    cudaGetSymbolAddress((void**)&bfrag, g_Bfrag);

    const int SMEM_A = 2 * 64 * A_STRIDE * (int)sizeof(__nv_bfloat16);  // 34816
    cudaFuncSetAttribute(gemm_mma_kernel,
                         cudaFuncAttributeMaxDynamicSharedMemorySize, SMEM_A);

    int gblocks = (num_atoms + 63) / 64;

    // 0) pack weights into mma B fragments (hi/lo)
    prep_weights_kernel<<<128, 256>>>(Win, Wout);

    // 1) zero conv accumulator (atomic targets + edgeless atoms)
    int nf4 = num_atoms * 32;
    zero_conv_kernel<<<(nf4 + 255) / 256, 256>>>(nf4);

    // 2) f = x @ W_in
    gemm_mma_kernel<<<gblocks, 256, SMEM_A>>>(
        x, bfrag + 0 * 8192, bfrag + 1 * 8192, nullptr, f_ptr, num_atoms);

    // 3) conv = segment_sum(w_ij * f[idx_j])   (edge-centric)
    int nwarps = (num_edges + EPW - 1) / EPW;
    conv_edge_kernel<<<(nwarps + 7) / 8, 256>>>(wij, idxj, seg, num_edges);

    // 4) out = conv @ W_out + b_out
    gemm_mma_kernel<<<gblocks, 256, SMEM_A>>>(
        conv_ptr, bfrag + 2 * 8192, bfrag + 3 * 8192, bout, (float*)d_out, num_atoms);
}